// round 12
// baseline (speedup 1.0000x reference)
#include <cuda_runtime.h>
#include <cuda_fp16.h>

#define NN   100000
#define FIN  256
#define HDIM 128
#define CDIM 64
#define MAXE 1600000
#define NCSR 148                  // scan-pipeline blocks (co-resident wave 1)
#define GB1  ((NN + 127) / 128)   // gemm1 tiles = 782
#define CB   391                  // histogram blocks in mega
#define ZB   128                  // tail-zero blocks in mega
#define ZD   ((NN + 255) / 256)   // deg-zero blocks appended to score

// Scratch (static device globals — allocation-free per harness rules)
__device__ int     g_degi[NN];              // zeroed at END of each call (k_score)
__device__ int     g_rowptr[NN + 1];
__device__ int     g_bsum[NCSR];
__device__ int     g_boff[NCSR];
__device__ int     g_cursor[NN];
__device__ int     g_esrc[MAXE];            // edge sources grouped by dst (CSR)
__device__ float   g_dis[NN];
__device__ __half2 g_hw1h[NN * HDIM / 2];   // fp16: (x@W1)[v]  (UNSCALED)
__device__ float   g_agg1[NN * HDIM];       // fp32: relu(layer-1 aggregate)
__device__ __half2 g_hw2h[NN * CDIM / 2];   // fp16: dis[v]*(agg1@W2)[v]
__device__ __half2 g_agg2h[NN * CDIM / 2];  // fp16: final h2
__device__ int     g_barc;                  // barrier arrive counter
__device__ int     g_barg;                  // barrier generation

__device__ __forceinline__ void cp_async16(void* smem, const void* gmem) {
    unsigned s = (unsigned)__cvta_generic_to_shared(smem);
    asm volatile("cp.async.ca.shared.global [%0], [%1], 16;\n" :: "r"(s), "l"(gmem));
}
__device__ __forceinline__ void cp_commit() { asm volatile("cp.async.commit_group;\n"); }
__device__ __forceinline__ void cp_wait0()  { asm volatile("cp.async.wait_group 0;\n" ::: "memory"); }

__device__ __forceinline__ unsigned f2tf32(float f) {
    unsigned u;
    asm("cvt.rna.tf32.f32 %0, %1;\n" : "=r"(u) : "f"(f));
    return u;
}

__device__ __forceinline__ void mma_tf32(float* d, const unsigned* a, const unsigned* b) {
    asm volatile(
        "mma.sync.aligned.m16n8k8.row.col.f32.tf32.tf32.f32 "
        "{%0,%1,%2,%3}, {%4,%5,%6,%7}, {%8,%9}, {%0,%1,%2,%3};\n"
        : "+f"(d[0]), "+f"(d[1]), "+f"(d[2]), "+f"(d[3])
        : "r"(a[0]), "r"(a[1]), "r"(a[2]), "r"(a[3]), "r"(b[0]), "r"(b[1]));
}

__device__ __forceinline__ void u4_to_f8(uint4 u, float* f) {
    float2 t;
    t = __half22float2(*(__half2*)&u.x); f[0] = t.x; f[1] = t.y;
    t = __half22float2(*(__half2*)&u.y); f[2] = t.x; f[3] = t.y;
    t = __half22float2(*(__half2*)&u.z); f[4] = t.x; f[5] = t.y;
    t = __half22float2(*(__half2*)&u.w); f[6] = t.x; f[7] = t.y;
}

// Grid barrier among NCSR co-resident blocks.
__device__ __forceinline__ void csr_barrier() {
    __syncthreads();
    if (threadIdx.x == 0) {
        int gen = atomicAdd(&g_barg, 0);
        __threadfence();
        int t = atomicAdd(&g_barc, 1);
        if (t == NCSR - 1) {
            atomicExch(&g_barc, 0);
            __threadfence();
            atomicAdd(&g_barg, 1);
        } else {
            while (atomicAdd(&g_barg, 0) == gen) { __nanosleep(64); }
        }
    }
    __syncthreads();
}

// ───────────────────────── TF32 tensor-core GEMM body ─────────────────────────
// SCALE_DIS ? C = fp16(dis[row]*(A@B)) : C = fp16(A@B).
// NOTE: g_* pointers must be resolved in DEVICE code (host shadow-symbol trap).
template<int BM, int BN, int BK, int WM, int WN, int NT, bool SCALE_DIS>
__device__ __forceinline__ void mma_body(
    int bx, const float* __restrict__ A, const float* __restrict__ Bg,
    __half2* __restrict__ C, int M, int N, int K)
{
    constexpr int BKp = BK + 4;
    constexpr int BNp = BN + 8;
    __shared__ float As[2][BM][BKp];
    __shared__ float Bs[2][BK][BNp];

    const int tid  = threadIdx.x;
    const int wid  = tid >> 5;
    const int lane = tid & 31;
    const int grp  = lane >> 2;
    const int qi   = lane & 3;
    constexpr int NWN = BN / WN;
    const int warp_m = wid / NWN;
    const int warp_n = wid % NWN;
    constexpr int MF = WM / 16;
    constexpr int NF = WN / 8;

    const int brow = bx * BM;

    float acc[MF][NF][4];
    #pragma unroll
    for (int i = 0; i < MF; i++)
        #pragma unroll
        for (int j = 0; j < NF; j++)
            #pragma unroll
            for (int q = 0; q < 4; q++) acc[i][j][q] = 0.0f;

    constexpr int AIT = (BM * BK / 4) / NT;
    constexpr int BIT = (BK * BN / 4) / NT;

    auto cpA = [&](int buf, int k0) {
        #pragma unroll
        for (int it = 0; it < AIT; it++) {
            int idx  = tid + it * NT;
            int row  = idx / (BK / 4);
            int kc   = (idx % (BK / 4)) * 4;
            int grow = brow + row;
            if (grow > M - 1) grow = M - 1;
            cp_async16(&As[buf][row][kc], A + (long long)grow * K + k0 + kc);
        }
    };
    auto cpB = [&](int buf, int k0) {
        #pragma unroll
        for (int it = 0; it < BIT; it++) {
            int idx = tid + it * NT;
            int kk  = idx / (BN / 4);
            int nc  = (idx % (BN / 4)) * 4;
            cp_async16(&Bs[buf][kk][nc], Bg + (long long)(k0 + kk) * N + nc);
        }
    };
    auto compute = [&](int buf) {
        #pragma unroll
        for (int ks = 0; ks < BK / 8; ks++) {
            int kk = ks * 8;
            unsigned a[MF][4], b[NF][2];
            #pragma unroll
            for (int fm = 0; fm < MF; fm++) {
                const float* ap = &As[buf][warp_m * WM + fm * 16 + grp][kk + qi];
                a[fm][0] = f2tf32(ap[0]);
                a[fm][1] = f2tf32(ap[8 * BKp]);
                a[fm][2] = f2tf32(ap[4]);
                a[fm][3] = f2tf32(ap[8 * BKp + 4]);
            }
            #pragma unroll
            for (int fn = 0; fn < NF; fn++) {
                const float* bp = &Bs[buf][kk + qi][warp_n * WN + fn * 8 + grp];
                b[fn][0] = f2tf32(bp[0]);
                b[fn][1] = f2tf32(bp[4 * BNp]);
            }
            #pragma unroll
            for (int fm = 0; fm < MF; fm++)
                #pragma unroll
                for (int fn = 0; fn < NF; fn++)
                    mma_tf32(acc[fm][fn], a[fm], b[fn]);
        }
    };

    cpA(0, 0); cpB(0, 0); cp_commit();
    cp_wait0(); __syncthreads();

    const int KT = K / BK;
    for (int t = 1; t < KT; t++) {
        cpA(t & 1, t * BK); cpB(t & 1, t * BK); cp_commit();
        compute((t - 1) & 1);
        cp_wait0(); __syncthreads();
    }
    compute((KT - 1) & 1);

    #pragma unroll
    for (int fm = 0; fm < MF; fm++) {
        int r0 = brow + warp_m * WM + fm * 16 + grp;
        int r1 = r0 + 8;
        float d0 = 1.0f, d1 = 1.0f;
        if (SCALE_DIS) {
            d0 = (r0 < M) ? g_dis[r0] : 0.0f;
            d1 = (r1 < M) ? g_dis[r1] : 0.0f;
        }
        #pragma unroll
        for (int fn = 0; fn < NF; fn++) {
            int col = warp_n * WN + fn * 8 + 2 * qi;
            if (r0 < M)
                C[((long long)r0 * N + col) >> 1] =
                    __floats2half2_rn(acc[fm][fn][0] * d0, acc[fm][fn][1] * d0);
            if (r1 < M)
                C[((long long)r1 * N + col) >> 1] =
                    __floats2half2_rn(acc[fm][fn][2] * d1, acc[fm][fn][3] * d1);
        }
    }
}

// ───────────────────────── mega: gemm1 ∥ histogram ∥ tail-zero ─────────────────
// g_degi enters this kernel ZEROED (invariant maintained by k_score's tail).
__global__ void __launch_bounds__(256)
k_mega(const float* __restrict__ x, const float* __restrict__ W1,
       const int* __restrict__ dst, int E,
       float* __restrict__ out, int SE, int total)
{
    int bx = blockIdx.x;
    if (bx < GB1) {   // gemm1: hw1h = fp16(x @ W1), unscaled
        mma_body<128, 128, 16, 64, 32, 256, false>(bx, x, W1, g_hw1h, NN, HDIM, FIN);
        return;
    }
    bx -= GB1;
    if (bx < CB) {    // degree histogram
        for (int e = bx * 256 + threadIdx.x; e < E; e += CB * 256)
            atomicAdd(&g_degi[dst[e]], 1);
        return;
    }
    bx -= CB;         // zero the tail of the output
    for (int i = SE + bx * 256 + threadIdx.x; i < total; i += ZB * 256)
        out[i] = 0.0f;
}

// ───────────────────────── fused 3-phase scan (148 blocks, grid barriers) ──────
__global__ void __launch_bounds__(256)
k_scan(int E)
{
    const int c   = blockIdx.x;
    const int tid = threadIdx.x;
    __shared__ int sc[256];
    const int chunk = (NN + NCSR - 1) / NCSR;
    const int lo = c * chunk;
    const int hi = (lo + chunk < NN) ? lo + chunk : NN;

    // Phase A: per-block chunk sums.
    {
        int s = 0;
        for (int i = lo + tid; i < hi; i += 256) s += g_degi[i];
        sc[tid] = s; __syncthreads();
        #pragma unroll
        for (int o = 128; o; o >>= 1) {
            if (tid < o) sc[tid] += sc[tid + o];
            __syncthreads();
        }
        if (tid == 0) g_bsum[c] = sc[0];
    }
    csr_barrier();

    // Phase B: block 0 exclusive-scans the chunk sums.
    if (c == 0) {
        int v = (tid < NCSR) ? g_bsum[tid] : 0;
        sc[tid] = v; __syncthreads();
        #pragma unroll
        for (int o = 1; o < 256; o <<= 1) {
            int t2 = (tid >= o) ? sc[tid - o] : 0;
            __syncthreads();
            sc[tid] += t2;
            __syncthreads();
        }
        if (tid < NCSR) g_boff[tid] = sc[tid] - v;
    }
    csr_barrier();

    // Phase C: rowptr / cursor / dis over the chunk.
    {
        int running = g_boff[c];
        for (int base = lo; base < hi; base += 256) {
            int i = base + tid;
            int d = (i < hi) ? g_degi[i] : 0;
            sc[tid] = d; __syncthreads();
            #pragma unroll
            for (int o = 1; o < 256; o <<= 1) {
                int t2 = (tid >= o) ? sc[tid - o] : 0;
                __syncthreads();
                sc[tid] += t2;
                __syncthreads();
            }
            if (i < hi) {
                int r = running + sc[tid] - d;
                g_rowptr[i] = r;
                g_cursor[i] = r;
                g_dis[i]    = rsqrtf((float)d + 1.0f);
            }
            running += sc[255];
            __syncthreads();
        }
        if (c == 0 && tid == 0) g_rowptr[NN] = E;
    }
}

__global__ void k_bin(const int* __restrict__ src, const int* __restrict__ dst, int E) {
    int e = blockIdx.x * blockDim.x + threadIdx.x;
    if (e >= E) return;
    int d = dst[e];
    int p = atomicAdd(&g_cursor[d], 1);
    g_esrc[p] = src[e];
}

// ───────────── gather aggregation: lean 32-reg bodies, 100% occupancy ──────────
// Layer 1: hw1h UNSCALED.  S = dv*h1[v] + Σ_e ds*h1[s];  agg1 = relu(dv*S + b1).
// 16 lanes per node, 1 uint4 per lane, 2-edge unroll, single accumulator set.
__global__ void __launch_bounds__(256, 8)
k_gather1(const float* __restrict__ b1) {
    int t = blockIdx.x * blockDim.x + threadIdx.x;
    int v = t >> 4, lane = t & 15;
    if (v >= NN) return;
    int beg = g_rowptr[v], end = g_rowptr[v + 1];
    float dv = g_dis[v];
    const uint4* hw = (const uint4*)g_hw1h;   // 16 uint4 per row

    float a[8];
    {
        float f[8];
        u4_to_f8(hw[(long long)v * 16 + lane], f);
        #pragma unroll
        for (int i = 0; i < 8; i++) a[i] = dv * f[i];
    }

    int p = beg;
    for (; p + 1 < end; p += 2) {
        int s0 = __ldg(&g_esrc[p]);
        int s1 = __ldg(&g_esrc[p + 1]);
        float d0 = g_dis[s0], d1 = g_dis[s1];
        uint4 u0 = hw[(long long)s0 * 16 + lane];
        uint4 u1 = hw[(long long)s1 * 16 + lane];
        float f0[8], f1[8];
        u4_to_f8(u0, f0); u4_to_f8(u1, f1);
        #pragma unroll
        for (int i = 0; i < 8; i++) a[i] = fmaf(d0, f0[i], a[i]);
        #pragma unroll
        for (int i = 0; i < 8; i++) a[i] = fmaf(d1, f1[i], a[i]);
    }
    if (p < end) {
        int s0 = __ldg(&g_esrc[p]);
        float d0 = g_dis[s0];
        float f0[8];
        u4_to_f8(hw[(long long)s0 * 16 + lane], f0);
        #pragma unroll
        for (int i = 0; i < 8; i++) a[i] = fmaf(d0, f0[i], a[i]);
    }
    float4 c0 = ((const float4*)b1)[lane * 2];
    float4 c1 = ((const float4*)b1)[lane * 2 + 1];
    float4* outp = (float4*)(g_agg1 + (long long)v * HDIM + lane * 8);
    outp[0] = make_float4(fmaxf(fmaf(dv, a[0], c0.x), 0.f),
                          fmaxf(fmaf(dv, a[1], c0.y), 0.f),
                          fmaxf(fmaf(dv, a[2], c0.z), 0.f),
                          fmaxf(fmaf(dv, a[3], c0.w), 0.f));
    outp[1] = make_float4(fmaxf(fmaf(dv, a[4], c1.x), 0.f),
                          fmaxf(fmaf(dv, a[5], c1.y), 0.f),
                          fmaxf(fmaf(dv, a[6], c1.z), 0.f),
                          fmaxf(fmaf(dv, a[7], c1.w), 0.f));
}

// Layer 2: hw2h pre-scaled by dis.  agg2 = fp16(dv*(hw2[v]+Σ hw2[s]) + b2).
// 8 lanes per node, 1 uint4 per lane, 2-edge unroll.
__global__ void __launch_bounds__(256, 8)
k_gather2(const float* __restrict__ b2) {
    int t = blockIdx.x * blockDim.x + threadIdx.x;
    int v = t >> 3, lane = t & 7;
    if (v >= NN) return;
    int beg = g_rowptr[v], end = g_rowptr[v + 1];
    float dv = g_dis[v];
    const uint4* hw = (const uint4*)g_hw2h;   // 8 uint4 per row

    float a[8];
    u4_to_f8(hw[(long long)v * 8 + lane], a);

    int p = beg;
    for (; p + 1 < end; p += 2) {
        int s0 = __ldg(&g_esrc[p]);
        int s1 = __ldg(&g_esrc[p + 1]);
        uint4 u0 = hw[(long long)s0 * 8 + lane];
        uint4 u1 = hw[(long long)s1 * 8 + lane];
        float f0[8], f1[8];
        u4_to_f8(u0, f0); u4_to_f8(u1, f1);
        #pragma unroll
        for (int i = 0; i < 8; i++) a[i] += f0[i] + f1[i];
    }
    if (p < end) {
        int s0 = __ldg(&g_esrc[p]);
        float f0[8];
        u4_to_f8(hw[(long long)s0 * 8 + lane], f0);
        #pragma unroll
        for (int i = 0; i < 8; i++) a[i] += f0[i];
    }
    float4 c0 = ((const float4*)b2)[lane * 2];
    float4 c1 = ((const float4*)b2)[lane * 2 + 1];
    uint4 u;
    *(__half2*)&u.x = __floats2half2_rn(fmaf(dv, a[0], c0.x), fmaf(dv, a[1], c0.y));
    *(__half2*)&u.y = __floats2half2_rn(fmaf(dv, a[2], c0.z), fmaf(dv, a[3], c0.w));
    *(__half2*)&u.z = __floats2half2_rn(fmaf(dv, a[4], c1.x), fmaf(dv, a[5], c1.y));
    *(__half2*)&u.w = __floats2half2_rn(fmaf(dv, a[6], c1.z), fmaf(dv, a[7], c1.w));
    ((uint4*)g_agg2h)[(long long)v * 8 + lane] = u;
}

// ──────── scoring (8 lanes/edge, 1 uint4 per side) + restore g_degi=0 ────────
__global__ void __launch_bounds__(256, 8)
k_score(const int* __restrict__ pos, const int* __restrict__ neg,
        int EPn, int SE, int sb, float* __restrict__ out)
{
    if ((int)blockIdx.x >= sb) {   // tail blocks: re-zero degree histogram
        int i = (blockIdx.x - sb) * 256 + threadIdx.x;
        if (i < NN) g_degi[i] = 0;
        return;
    }
    int t = blockIdx.x * blockDim.x + threadIdx.x;
    int e = t >> 3, lane = t & 7;
    if (e >= SE) return;
    int i, j;
    if (e < EPn) { j = pos[e];       i = pos[e + EPn]; }
    else         { j = neg[e - EPn]; i = neg[e];       }
    const uint4* h4 = (const uint4*)g_agg2h;
    uint4 ua = h4[(long long)i * 8 + lane];
    uint4 ub = h4[(long long)j * 8 + lane];
    float fa[8], fb[8];
    u4_to_f8(ua, fa);
    u4_to_f8(ub, fb);
    float s = 0.f;
    #pragma unroll
    for (int q = 0; q < 8; q++) s = fmaf(fa[q], fb[q], s);
    #pragma unroll
    for (int o = 4; o; o >>= 1) s += __shfl_xor_sync(0xffffffffu, s, o);
    if (lane == 0) out[e] = s;
}

// ───────────────────────── gemm2 wrapper ─────────────────────────
__global__ void __launch_bounds__(256)
k_gemm2(const float* __restrict__ W2)
{
    mma_body<128, 64, 16, 32, 32, 256, true>(blockIdx.x, g_agg1, W2, g_hw2h,
                                             NN, CDIM, HDIM);
}

extern "C" void kernel_launch(void* const* d_in, const int* in_sizes, int n_in,
                              void* d_out, int out_size)
{
    const float* x   = (const float*)d_in[0];
    // d_in[1] = masked_nodes (unused by the reference output)
    const int*   pos = (const int*)d_in[2];
    const int*   neg = (const int*)d_in[3];
    const int*   ei  = (const int*)d_in[4];
    const float* W1  = (const float*)d_in[5];
    const float* b1  = (const float*)d_in[6];
    const float* W2  = (const float*)d_in[7];
    const float* b2  = (const float*)d_in[8];
    float* out = (float*)d_out;

    const int E   = in_sizes[4] / 2;
    const int EPn = in_sizes[2] / 2;
    const int SE  = 2 * EPn;
    const int* src = ei;
    const int* dst = ei + E;

    // gemm1 ∥ degree histogram ∥ output-tail zeroing
    k_mega<<<GB1 + CB + ZB, 256>>>(x, W1, dst, E, out, SE, out_size);

    // fused 3-phase prefix scan (rowptr/cursor/dis)
    k_scan<<<NCSR, 256>>>(E);
    k_bin <<<(E + 255) / 256, 256>>>(src, dst, E);

    k_gather1<<<(NN * 16 + 255) / 256, 256>>>(b1);

    k_gemm2<<<(NN + 127) / 128, 256>>>(W2);
    k_gather2<<<(NN * 8 + 255) / 256, 256>>>(b2);

    const int sb = (SE * 8 + 255) / 256;
    k_score<<<sb + ZD, 256>>>(pos, neg, EPn, SE, sb, out);
}